// round 7
// baseline (speedup 1.0000x reference)
#include <cuda_runtime.h>
#include <cstdint>
#include <math.h>

#define N_LEVELS 16
#define LOG2_T 19
#define TABLE_SIZE (1u << LOG2_T)
#define TABLE_MASK (TABLE_SIZE - 1u)

#define THREADS 256

struct ResParams { float resm1[N_LEVELS]; };

// 8 lanes per point: lane-group k handles levels 2k and 2k+1 and writes one
// float4 of the output row. Global float4 index == global thread id, so every
// warp's STG.128 covers 512 contiguous bytes (4 L1tex wavefronts, the floor).
// Gathers use __ldcg (L2-only caching): table misses dominate (64MB >> L1),
// so skipping L1 allocation removes ~33M x 128B of L1 line-fill traffic from
// the binding l1tex pipe at the cost of a few coarse-level L1 hits.
__global__ void __launch_bounds__(THREADS) hashgrid_kernel(
    const float* __restrict__ x,
    const float2* __restrict__ tables,
    float4* __restrict__ out,
    int n, ResParams rp)
{
    const int tid = blockIdx.x * THREADS + threadIdx.x;
    const int p   = tid >> 3;       // point index
    const int k   = tid & 7;        // float4 slot within the output row
    if (p >= n) return;

    // 8 lanes share these addresses -> L1 broadcast, ~free. Keep L1-cached.
    const float px = __ldg(&x[3 * p + 0]);
    const float py = __ldg(&x[3 * p + 1]);
    const float pz = __ldg(&x[3 * p + 2]);

    // Match reference: x_norm = (x + 1) / 2 in f32 (no FMA contraction)
    const float xn = __fmul_rn(__fadd_rn(px, 1.0f), 0.5f);
    const float yn = __fmul_rn(__fadd_rn(py, 1.0f), 0.5f);
    const float zn = __fmul_rn(__fadd_rn(pz, 1.0f), 0.5f);

    const int l0 = 2 * k;
    const int l1 = 2 * k + 1;

    const float r0 = rp.resm1[l0];
    const float r1 = rp.resm1[l1];

    // scaled = x_norm * (res - 1); truncating cast == floor (operands >= 0)
    const uint32_t gx0 = (uint32_t)__fmul_rn(xn, r0);
    const uint32_t gy0 = (uint32_t)__fmul_rn(yn, r0);
    const uint32_t gz0 = (uint32_t)__fmul_rn(zn, r0);
    const uint32_t gx1 = (uint32_t)__fmul_rn(xn, r1);
    const uint32_t gy1 = (uint32_t)__fmul_rn(yn, r1);
    const uint32_t gz1 = (uint32_t)__fmul_rn(zn, r1);

    const uint32_t h0 =
        (gx0 ^ (gy0 * 2654435761u) ^ (gz0 * 805459861u)) & TABLE_MASK;
    const uint32_t h1 =
        (gx1 ^ (gy1 * 2654435761u) ^ (gz1 * 805459861u)) & TABLE_MASK;

    // L2-only gathers: no L1 line allocation/fill.
    const float2 f0 = __ldcg(&tables[(size_t)l0 * TABLE_SIZE + h0]);
    const float2 f1 = __ldcg(&tables[(size_t)l1 * TABLE_SIZE + h1]);

    out[(size_t)tid] = make_float4(f0.x, f0.y, f1.x, f1.y);
}

extern "C" void kernel_launch(void* const* d_in, const int* in_sizes, int n_in,
                              void* d_out, int out_size)
{
    const float*  x      = (const float*)d_in[0];
    const float2* tables = (const float2*)d_in[1];
    float4*       out    = (float4*)d_out;

    const int n = in_sizes[0] / 3;  // x has N*3 elements

    // Resolutions via the same double-precision libm chain as the Python
    // reference: b = exp((log(2048) - log(16)) / 15); res_l = int(16 * b**l).
    // Proven bit-identical (rel_err == 0.0) in prior rounds.
    ResParams rp;
    {
        const double b = exp((log(2048.0) - log(16.0)) / 15.0);
        for (int l = 0; l < N_LEVELS; l++) {
            int res = (int)(16.0 * pow(b, (double)l));
            rp.resm1[l] = (float)res - 1.0f;
        }
    }

    const long long total = (long long)n * 8;            // one thread per float4
    const int blocks = (int)((total + THREADS - 1) / THREADS);
    hashgrid_kernel<<<blocks, THREADS>>>(x, tables, out, n, rp);
}

// round 8
// speedup vs baseline: 1.0256x; 1.0256x over previous
#include <cuda_runtime.h>
#include <cstdint>
#include <math.h>

#define N_LEVELS 16
#define LOG2_T 19
#define TABLE_SIZE (1u << LOG2_T)
#define TABLE_MASK (TABLE_SIZE - 1u)

#define THREADS 256

struct ResParams { float resm1[N_LEVELS]; };

// 8 lanes per point: lane-group k handles levels 2k and 2k+1 and writes one
// float4 of the output row. Global float4 index == global thread id, so every
// warp's STG.128 covers 512 contiguous bytes (4 L1tex wavefronts, the floor).
// Gathers via __ldg (proven best R6); output via __stcs (evict-first) so the
// 256MB write-once stream doesn't evict the 64MB table from L2.
__global__ void __launch_bounds__(THREADS) hashgrid_kernel(
    const float* __restrict__ x,
    const float2* __restrict__ tables,
    float4* __restrict__ out,
    int n, ResParams rp)
{
    const int tid = blockIdx.x * THREADS + threadIdx.x;
    const int p   = tid >> 3;       // point index
    const int k   = tid & 7;        // float4 slot within the output row
    if (p >= n) return;

    // 8 lanes share these addresses -> L1 broadcast, ~free.
    const float px = __ldg(&x[3 * p + 0]);
    const float py = __ldg(&x[3 * p + 1]);
    const float pz = __ldg(&x[3 * p + 2]);

    // Match reference: x_norm = (x + 1) / 2 in f32 (no FMA contraction)
    const float xn = __fmul_rn(__fadd_rn(px, 1.0f), 0.5f);
    const float yn = __fmul_rn(__fadd_rn(py, 1.0f), 0.5f);
    const float zn = __fmul_rn(__fadd_rn(pz, 1.0f), 0.5f);

    const int l0 = 2 * k;
    const int l1 = 2 * k + 1;

    const float r0 = rp.resm1[l0];
    const float r1 = rp.resm1[l1];

    // scaled = x_norm * (res - 1); truncating cast == floor (operands >= 0)
    const uint32_t gx0 = (uint32_t)__fmul_rn(xn, r0);
    const uint32_t gy0 = (uint32_t)__fmul_rn(yn, r0);
    const uint32_t gz0 = (uint32_t)__fmul_rn(zn, r0);
    const uint32_t gx1 = (uint32_t)__fmul_rn(xn, r1);
    const uint32_t gy1 = (uint32_t)__fmul_rn(yn, r1);
    const uint32_t gz1 = (uint32_t)__fmul_rn(zn, r1);

    const uint32_t h0 =
        (gx0 ^ (gy0 * 2654435761u) ^ (gz0 * 805459861u)) & TABLE_MASK;
    const uint32_t h1 =
        (gx1 ^ (gy1 * 2654435761u) ^ (gz1 * 805459861u)) & TABLE_MASK;

    const float2 f0 = __ldg(&tables[(size_t)l0 * TABLE_SIZE + h0]);
    const float2 f1 = __ldg(&tables[(size_t)l1 * TABLE_SIZE + h1]);

    // Evict-first store: output is write-once, never re-read.
    __stcs(&out[(size_t)tid], make_float4(f0.x, f0.y, f1.x, f1.y));
}

extern "C" void kernel_launch(void* const* d_in, const int* in_sizes, int n_in,
                              void* d_out, int out_size)
{
    const float*  x      = (const float*)d_in[0];
    const float2* tables = (const float2*)d_in[1];
    float4*       out    = (float4*)d_out;

    const int n = in_sizes[0] / 3;  // x has N*3 elements

    // Resolutions via the same double-precision libm chain as the Python
    // reference: b = exp((log(2048) - log(16)) / 15); res_l = int(16 * b**l).
    // Proven bit-identical (rel_err == 0.0) in prior rounds.
    ResParams rp;
    {
        const double b = exp((log(2048.0) - log(16.0)) / 15.0);
        for (int l = 0; l < N_LEVELS; l++) {
            int res = (int)(16.0 * pow(b, (double)l));
            rp.resm1[l] = (float)res - 1.0f;
        }
    }

    const long long total = (long long)n * 8;            // one thread per float4
    const int blocks = (int)((total + THREADS - 1) / THREADS);
    hashgrid_kernel<<<blocks, THREADS>>>(x, tables, out, n, rp);
}